// round 2
// baseline (speedup 1.0000x reference)
#include <cuda_runtime.h>

// JumpEulerForwardCuda — persistent per-thread SDE simulation, fp32 with
// packed fma.rn.f32x2 (FFMA2) for 2x FMA throughput on the fma pipe.
//
// One thread = one simulation path. Weights packed into shared memory as
// f32x2 pairs along the reduction (input) dimension; each ffma2 accumulates
// two partial products in the lo/hi halves of a 64-bit accumulator, reduced
// once per output neuron. Layers 2/3 process 4 outputs per inner iteration
// (4 independent FFMA2 chains) to hide LDS/FMA latency at 1 warp/SMSP.

typedef unsigned long long u64;

#define D      10
#define H      64
#define DPAIR  5    // D/2
#define HPAIR  32   // H/2
#define BLOCK  128

#define DT_F     0.03f
#define SQDT_F   0.17320508075688772f   // sqrt(0.03)

__device__ __forceinline__ u64 pack2(float lo, float hi) {
    u64 r;
    asm("mov.b64 %0, {%1, %2};" : "=l"(r) : "f"(lo), "f"(hi));
    return r;
}
__device__ __forceinline__ void unpack2(u64 v, float& lo, float& hi) {
    asm("mov.b64 {%0, %1}, %2;" : "=f"(lo), "=f"(hi) : "l"(v));
}
__device__ __forceinline__ void ffma2(u64& d, u64 a, u64 b) {
    asm("fma.rn.f32x2 %0, %1, %2, %0;" : "+l"(d) : "l"(a), "l"(b));
}
__device__ __forceinline__ float hsum(u64 v) {
    float a, b; unpack2(v, a, b); return a + b;
}
// leaky_relu(x, 0.01) == max(x, 0.01*x) exactly
__device__ __forceinline__ float leaky(float x) { return fmaxf(x, 0.01f * x); }

struct __align__(16) MLPW {
    u64  W0[H][DPAIR];   // {W0[2i][j], W0[2i+1][j]}
    u64  W1[H][HPAIR];   // {W1[2i][j], W1[2i+1][j]}  (row = output j, 256B)
    u64  W2[D][HPAIR];   // {W2[2i][k], W2[2i+1][k]}
    u64  B0[H];          // {b0[j], 0}
    u64  B1[H];          // {b1[j], 0}
    float B2[D];
};

__shared__ __align__(16) MLPW s_drift;
__shared__ __align__(16) MLPW s_jump;
__shared__ u64   s_cov[D][DPAIR];     // {cov[2i][k], cov[2i+1][k]}
__shared__ float s_mean[D];
__shared__ float s_diff[2][D];        // diffusion rows (bd = 2)

__device__ __forceinline__ void fill_mlp(
    MLPW& s,
    const float* __restrict__ W0, const float* __restrict__ b0,
    const float* __restrict__ W1, const float* __restrict__ b1,
    const float* __restrict__ W2, const float* __restrict__ b2,
    int tid)
{
    for (int idx = tid; idx < H * DPAIR; idx += BLOCK) {
        int j = idx / DPAIR, ip = idx % DPAIR;
        s.W0[j][ip] = pack2(W0[(2 * ip) * H + j], W0[(2 * ip + 1) * H + j]);
    }
    for (int idx = tid; idx < H * HPAIR; idx += BLOCK) {
        int j = idx / HPAIR, ip = idx % HPAIR;
        s.W1[j][ip] = pack2(W1[(2 * ip) * H + j], W1[(2 * ip + 1) * H + j]);
    }
    for (int idx = tid; idx < D * HPAIR; idx += BLOCK) {
        int k = idx / HPAIR, ip = idx % HPAIR;
        s.W2[k][ip] = pack2(W2[(2 * ip) * D + k], W2[(2 * ip + 1) * D + k]);
    }
    for (int j = tid; j < H; j += BLOCK) {
        s.B0[j] = pack2(b0[j], 0.0f);
        s.B1[j] = pack2(b1[j], 0.0f);
    }
    for (int k = tid; k < D; k += BLOCK) s.B2[k] = b2[k];
}

// x: packed input pairs (D floats in DPAIR u64s). out: D floats.
__device__ __forceinline__ void run_mlp(const MLPW& w, const u64 zp[DPAIR], float out[D])
{
    // Layer 1: D -> H, leaky. 4 outputs / iteration (4 independent chains).
    u64 h1p[HPAIR];
    #pragma unroll
    for (int j0 = 0; j0 < H; j0 += 4) {
        u64 a0 = w.B0[j0];
        u64 a1 = w.B0[j0 + 1];
        u64 a2 = w.B0[j0 + 2];
        u64 a3 = w.B0[j0 + 3];
        #pragma unroll
        for (int ip = 0; ip < DPAIR; ip++) {
            u64 zv = zp[ip];
            ffma2(a0, zv, w.W0[j0][ip]);
            ffma2(a1, zv, w.W0[j0 + 1][ip]);
            ffma2(a2, zv, w.W0[j0 + 2][ip]);
            ffma2(a3, zv, w.W0[j0 + 3][ip]);
        }
        h1p[j0 / 2]     = pack2(leaky(hsum(a0)), leaky(hsum(a1)));
        h1p[j0 / 2 + 1] = pack2(leaky(hsum(a2)), leaky(hsum(a3)));
    }

    // Layer 2: H -> H, leaky. 4 outputs / iteration.
    u64 h2p[HPAIR];
    #pragma unroll
    for (int j0 = 0; j0 < H; j0 += 4) {
        u64 a0 = w.B1[j0];
        u64 a1 = w.B1[j0 + 1];
        u64 a2 = w.B1[j0 + 2];
        u64 a3 = w.B1[j0 + 3];
        const ulonglong2* w0 = (const ulonglong2*)(&w.W1[j0][0]);
        const ulonglong2* w1 = (const ulonglong2*)(&w.W1[j0 + 1][0]);
        const ulonglong2* w2 = (const ulonglong2*)(&w.W1[j0 + 2][0]);
        const ulonglong2* w3 = (const ulonglong2*)(&w.W1[j0 + 3][0]);
        #pragma unroll
        for (int ip2 = 0; ip2 < HPAIR / 2; ip2++) {
            u64 hA = h1p[2 * ip2];
            u64 hB = h1p[2 * ip2 + 1];
            ulonglong2 wa = w0[ip2];
            ulonglong2 wb = w1[ip2];
            ulonglong2 wc = w2[ip2];
            ulonglong2 wd = w3[ip2];
            ffma2(a0, hA, wa.x); ffma2(a0, hB, wa.y);
            ffma2(a1, hA, wb.x); ffma2(a1, hB, wb.y);
            ffma2(a2, hA, wc.x); ffma2(a2, hB, wc.y);
            ffma2(a3, hA, wd.x); ffma2(a3, hB, wd.y);
        }
        h2p[j0 / 2]     = pack2(leaky(hsum(a0)), leaky(hsum(a1)));
        h2p[j0 / 2 + 1] = pack2(leaky(hsum(a2)), leaky(hsum(a3)));
    }

    // Layer 3: H -> D, linear. 2 outputs / iteration (D=10).
    #pragma unroll
    for (int k = 0; k < D; k += 2) {
        u64 a0 = 0ULL;
        u64 a1 = 0ULL;
        const ulonglong2* wk0 = (const ulonglong2*)(&w.W2[k][0]);
        const ulonglong2* wk1 = (const ulonglong2*)(&w.W2[k + 1][0]);
        #pragma unroll
        for (int ip2 = 0; ip2 < HPAIR / 2; ip2++) {
            u64 hA = h2p[2 * ip2];
            u64 hB = h2p[2 * ip2 + 1];
            ulonglong2 wa = wk0[ip2];
            ulonglong2 wb = wk1[ip2];
            ffma2(a0, hA, wa.x); ffma2(a0, hB, wa.y);
            ffma2(a1, hA, wb.x); ffma2(a1, hB, wb.y);
        }
        out[k]     = hsum(a0) + w.B2[k];
        out[k + 1] = hsum(a1) + w.B2[k + 1];
    }
}

__global__ void __launch_bounds__(BLOCK)
jump_euler_kernel(
    const float* __restrict__ z0,
    const float* __restrict__ dW0, const float* __restrict__ db0,
    const float* __restrict__ dW1, const float* __restrict__ db1,
    const float* __restrict__ dW2, const float* __restrict__ db2,
    const float* __restrict__ jW0, const float* __restrict__ jb0,
    const float* __restrict__ jW1, const float* __restrict__ jb1,
    const float* __restrict__ jW2, const float* __restrict__ jb2,
    const float* __restrict__ mean, const float* __restrict__ cov,
    const float* __restrict__ diff,
    const float* __restrict__ pois, const float* __restrict__ nbd,
    const float* __restrict__ nd,
    float* __restrict__ out, int Nsim, int steps)
{
    int tid = threadIdx.x;

    fill_mlp(s_drift, dW0, db0, dW1, db1, dW2, db2, tid);
    fill_mlp(s_jump,  jW0, jb0, jW1, jb1, jW2, jb2, tid);
    for (int idx = tid; idx < D * DPAIR; idx += BLOCK) {
        int k = idx / DPAIR, ip = idx % DPAIR;
        s_cov[k][ip] = pack2(cov[(2 * ip) * D + k], cov[(2 * ip + 1) * D + k]);
    }
    if (tid < D) {
        s_mean[tid]    = mean[tid];
        s_diff[0][tid] = diff[tid];
        s_diff[1][tid] = diff[D + tid];
    }
    __syncthreads();

    int sim = blockIdx.x * BLOCK + tid;
    if (sim >= Nsim) return;

    float z[D];
    float* orow = out + (size_t)sim * (size_t)(steps + 1) * D;
    {
        const float2* z0v = (const float2*)(z0 + (size_t)sim * D);
        #pragma unroll
        for (int ip = 0; ip < DPAIR; ip++) {
            float2 v = z0v[ip];
            z[2 * ip] = v.x; z[2 * ip + 1] = v.y;
            ((float2*)orow)[ip] = v;   // path[:,0,:] = z0
        }
    }

    for (int t = 0; t < steps; t++) {
        size_t base = (size_t)t * Nsim + sim;
        // Issue all global loads for this step up-front; they are consumed
        // only after ~10K cycles of MLP math, so DRAM latency is hidden.
        float p = pois[base];
        float2 nb = *(const float2*)(nbd + base * 2);
        u64 ndp[DPAIR];
        {
            const float2* ndv = (const float2*)(nd + base * D);
            #pragma unroll
            for (int ip = 0; ip < DPAIR; ip++) {
                float2 v = ndv[ip];
                ndp[ip] = pack2(v.x, v.y);
            }
        }

        u64 zp[DPAIR];
        #pragma unroll
        for (int ip = 0; ip < DPAIR; ip++) zp[ip] = pack2(z[2 * ip], z[2 * ip + 1]);

        float drift[D], jmlp[D];
        run_mlp(s_drift, zp, drift);
        run_mlp(s_jump,  zp, jmlp);

        float sp = sqrtf(p);
        float* orow_t = orow + (size_t)(t + 1) * D;
        #pragma unroll
        for (int k = 0; k < D; k++) {
            // covk = (nd @ covHalf)[k]
            u64 a = 0ULL;
            #pragma unroll
            for (int ip = 0; ip < DPAIR; ip++) ffma2(a, ndp[ip], s_cov[k][ip]);
            float covk = hsum(a);
            float ja  = fmaf(p, s_mean[k], sp * covk);                  // jump_amp
            float dif = fmaf(nb.x, s_diff[0][k], nb.y * s_diff[1][k]);  // nbd @ diffusion
            float nz = fmaf(drift[k], DT_F, z[k]);
            nz = fmaf(SQDT_F, dif, nz);
            nz = fmaf(ja, jmlp[k], nz);
            z[k] = nz;
        }
        #pragma unroll
        for (int ip = 0; ip < DPAIR; ip++) {
            float2 v; v.x = z[2 * ip]; v.y = z[2 * ip + 1];
            ((float2*)orow_t)[ip] = v;
        }
    }
}

extern "C" void kernel_launch(void* const* d_in, const int* in_sizes, int n_in,
                              void* d_out, int out_size)
{
    // metadata order:
    // 0 z0, 1 dW0, 2 db0, 3 dW1, 4 db1, 5 dW2, 6 db2,
    // 7 jW0, 8 jb0, 9 jW1, 10 jb1, 11 jW2, 12 jb2,
    // 13 mean, 14 covHalf, 15 diffusion, 16 pois, 17 noise_bd, 18 noise_d, 19 steps
    const float* z0  = (const float*)d_in[0];
    const float* dW0 = (const float*)d_in[1];
    const float* db0 = (const float*)d_in[2];
    const float* dW1 = (const float*)d_in[3];
    const float* db1 = (const float*)d_in[4];
    const float* dW2 = (const float*)d_in[5];
    const float* db2 = (const float*)d_in[6];
    const float* jW0 = (const float*)d_in[7];
    const float* jb0 = (const float*)d_in[8];
    const float* jW1 = (const float*)d_in[9];
    const float* jb1 = (const float*)d_in[10];
    const float* jW2 = (const float*)d_in[11];
    const float* jb2 = (const float*)d_in[12];
    const float* mean = (const float*)d_in[13];
    const float* cov  = (const float*)d_in[14];
    const float* diff = (const float*)d_in[15];
    const float* pois = (const float*)d_in[16];
    const float* nbd  = (const float*)d_in[17];
    const float* nd   = (const float*)d_in[18];

    int Nsim  = in_sizes[0] / D;
    int steps = in_sizes[16] / Nsim;

    int grid = (Nsim + BLOCK - 1) / BLOCK;
    jump_euler_kernel<<<grid, BLOCK>>>(
        z0, dW0, db0, dW1, db1, dW2, db2,
        jW0, jb0, jW1, jb1, jW2, jb2,
        mean, cov, diff, pois, nbd, nd,
        (float*)d_out, Nsim, steps);
}

// round 4
// speedup vs baseline: 2.3887x; 2.3887x over previous
#include <cuda_runtime.h>

// JumpEulerForwardCuda — persistent SDE simulation, 2 lanes per path.
// fp32 via packed fma.rn.f32x2 (FFMA2). Each lane of a pair owns 32 of the
// 64 hidden neurons; halves are exchanged with warp shuffles at layer
// boundaries. This halves the register-resident activation state (no spills)
// and doubles warps/SMSP vs the 1-thread-per-path version.

typedef unsigned long long u64;

#define D      10
#define H      64
#define DPAIR  5     // D/2
#define HPAIR  32    // H/2
#define HHALF  32    // neurons owned per lane
#define BLOCK  256   // 8 warps -> 2 warps per SMSP, 1 persistent CTA per SM

#define DT_F     0.03f
#define SQDT_F   0.17320508075688772f   // sqrt(0.03)

// Skew: odd lane's weight rows are offset +16B (2 u64) so even/odd lanes hit
// disjoint shared-memory banks. (Row-pair distances 1280B / 8192B are
// multiples of 128B -> same banks without skew.) 16B keeps LDS.128 alignment.
#define W0_HALF_OFF  (HHALF * DPAIR + 2)   // u64 units
#define W1_HALF_OFF  (HHALF * HPAIR + 2)
#define W2_HALF_OFF  (5 * HPAIR + 2)
#define B_HALF_OFF   (HHALF + 2)

__device__ __forceinline__ u64 pack2(float lo, float hi) {
    u64 r;
    asm("mov.b64 %0, {%1, %2};" : "=l"(r) : "f"(lo), "f"(hi));
    return r;
}
__device__ __forceinline__ void unpack2(u64 v, float& lo, float& hi) {
    asm("mov.b64 {%0, %1}, %2;" : "=f"(lo), "=f"(hi) : "l"(v));
}
__device__ __forceinline__ void ffma2(u64& d, u64 a, u64 b) {
    asm("fma.rn.f32x2 %0, %1, %2, %0;" : "+l"(d) : "l"(a), "l"(b));
}
__device__ __forceinline__ float hsum(u64 v) {
    float a, b; unpack2(v, a, b); return a + b;
}
// leaky_relu(x, 0.01) == max(x, 0.01*x) exactly
__device__ __forceinline__ float leaky(float x) { return fmaxf(x, 0.01f * x); }
__device__ __forceinline__ u64 shfl1(u64 v) {
    return __shfl_xor_sync(0xFFFFFFFFu, v, 1);
}
__device__ __forceinline__ float shfl1f(float v) {
    return __shfl_xor_sync(0xFFFFFFFFu, v, 1);
}

struct __align__(16) MLPW {
    u64  W1[H * HPAIR + 2];   // row j at j*HPAIR + (j>=32 ? 2 : 0); pairs along input
    u64  W0[H * DPAIR + 2];   // row j at j*DPAIR + (j>=32 ? 2 : 0)
    u64  W2[D * HPAIR + 2];   // row k at k*HPAIR + (k>=5  ? 2 : 0)
    u64  B0[H + 2];           // j + (j>=32 ? 2 : 0), value {b, 0}
    u64  B1[H + 2];
    float B2[D];
};

__shared__ __align__(16) MLPW s_drift;
__shared__ __align__(16) MLPW s_jump;
__shared__ u64   s_cov[D][DPAIR];     // {cov[2i][k], cov[2i+1][k]}
__shared__ float s_mean[D];
__shared__ float s_diff[2][D];        // diffusion rows (bd = 2)

__device__ __forceinline__ void fill_mlp(
    MLPW& s,
    const float* __restrict__ W0, const float* __restrict__ b0,
    const float* __restrict__ W1, const float* __restrict__ b1,
    const float* __restrict__ W2, const float* __restrict__ b2,
    int tid)
{
    for (int idx = tid; idx < H * DPAIR; idx += BLOCK) {
        int j = idx / DPAIR, ip = idx % DPAIR;
        s.W0[idx + (j >= HHALF ? 2 : 0)] =
            pack2(W0[(2 * ip) * H + j], W0[(2 * ip + 1) * H + j]);
    }
    for (int idx = tid; idx < H * HPAIR; idx += BLOCK) {
        int j = idx / HPAIR, ip = idx % HPAIR;
        s.W1[idx + (j >= HHALF ? 2 : 0)] =
            pack2(W1[(2 * ip) * H + j], W1[(2 * ip + 1) * H + j]);
    }
    for (int idx = tid; idx < D * HPAIR; idx += BLOCK) {
        int k = idx / HPAIR, ip = idx % HPAIR;
        s.W2[idx + (k >= 5 ? 2 : 0)] =
            pack2(W2[(2 * ip) * D + k], W2[(2 * ip + 1) * D + k]);
    }
    for (int j = tid; j < H; j += BLOCK) {
        s.B0[j + (j >= HHALF ? 2 : 0)] = pack2(b0[j], 0.0f);
        s.B1[j + (j >= HHALF ? 2 : 0)] = pack2(b1[j], 0.0f);
    }
    for (int k = tid; k < D; k += BLOCK) s.B2[k] = b2[k];
}

// One MLP, cooperative pair. zp: full packed input (5 u64). out: this lane's
// 5 output components (k = half*5 + k0).
__device__ __forceinline__ void run_mlp(const MLPW& w, int half,
                                        const u64 zp[DPAIR], float out[5])
{
    const u64* w0b = w.W0 + half * W0_HALF_OFF;
    const u64* w1b = w.W1 + half * W1_HALF_OFF;
    const u64* w2b = w.W2 + half * W2_HALF_OFF;
    const u64* b0b = w.B0 + half * B_HALF_OFF;
    const u64* b1b = w.B1 + half * B_HALF_OFF;

    // ---- Layer 1: D -> 32 own neurons, leaky ----
    u64 h1own[HHALF / 2];
    #pragma unroll
    for (int j0 = 0; j0 < HHALF; j0 += 4) {
        u64 a0 = b0b[j0];
        u64 a1 = b0b[j0 + 1];
        u64 a2 = b0b[j0 + 2];
        u64 a3 = b0b[j0 + 3];
        #pragma unroll
        for (int ip = 0; ip < DPAIR; ip++) {
            u64 zv = zp[ip];
            ffma2(a0, zv, w0b[(j0 + 0) * DPAIR + ip]);
            ffma2(a1, zv, w0b[(j0 + 1) * DPAIR + ip]);
            ffma2(a2, zv, w0b[(j0 + 2) * DPAIR + ip]);
            ffma2(a3, zv, w0b[(j0 + 3) * DPAIR + ip]);
        }
        h1own[j0 / 2]     = pack2(leaky(hsum(a0)), leaky(hsum(a1)));
        h1own[j0 / 2 + 1] = pack2(leaky(hsum(a2)), leaky(hsum(a3)));
    }

    // ---- Exchange: assemble full h1 (compile-time indices only) ----
    u64 h1f[HPAIR];
    #pragma unroll
    for (int i = 0; i < HHALF / 2; i++) {
        u64 a = h1own[i];
        u64 b = shfl1(a);
        h1f[i]              = half ? b : a;   // neurons 0..31
        h1f[HHALF / 2 + i]  = half ? a : b;   // neurons 32..63
    }

    // ---- Layer 2: 64 -> 32 own neurons, leaky ----
    u64 h2own[HHALF / 2];
    #pragma unroll
    for (int j0 = 0; j0 < HHALF; j0 += 4) {
        u64 a0 = b1b[j0];
        u64 a1 = b1b[j0 + 1];
        u64 a2 = b1b[j0 + 2];
        u64 a3 = b1b[j0 + 3];
        const ulonglong2* r0 = (const ulonglong2*)(w1b + (j0 + 0) * HPAIR);
        const ulonglong2* r1 = (const ulonglong2*)(w1b + (j0 + 1) * HPAIR);
        const ulonglong2* r2 = (const ulonglong2*)(w1b + (j0 + 2) * HPAIR);
        const ulonglong2* r3 = (const ulonglong2*)(w1b + (j0 + 3) * HPAIR);
        #pragma unroll
        for (int ip2 = 0; ip2 < HPAIR / 2; ip2++) {
            u64 hA = h1f[2 * ip2];
            u64 hB = h1f[2 * ip2 + 1];
            ulonglong2 wa = r0[ip2];
            ulonglong2 wb = r1[ip2];
            ulonglong2 wc = r2[ip2];
            ulonglong2 wd = r3[ip2];
            ffma2(a0, hA, wa.x); ffma2(a0, hB, wa.y);
            ffma2(a1, hA, wb.x); ffma2(a1, hB, wb.y);
            ffma2(a2, hA, wc.x); ffma2(a2, hB, wc.y);
            ffma2(a3, hA, wd.x); ffma2(a3, hB, wd.y);
        }
        h2own[j0 / 2]     = pack2(leaky(hsum(a0)), leaky(hsum(a1)));
        h2own[j0 / 2 + 1] = pack2(leaky(hsum(a2)), leaky(hsum(a3)));
    }

    // ---- Exchange: assemble full h2 ----
    u64 h2f[HPAIR];
    #pragma unroll
    for (int i = 0; i < HHALF / 2; i++) {
        u64 a = h2own[i];
        u64 b = shfl1(a);
        h2f[i]             = half ? b : a;
        h2f[HHALF / 2 + i] = half ? a : b;
    }

    // ---- Layer 3: 64 -> 5 own outputs, linear ----
    u64 acc[5];
    #pragma unroll
    for (int k0 = 0; k0 < 5; k0++) acc[k0] = 0ULL;
    #pragma unroll
    for (int ip2 = 0; ip2 < HPAIR / 2; ip2++) {
        u64 hA = h2f[2 * ip2];
        u64 hB = h2f[2 * ip2 + 1];
        #pragma unroll
        for (int k0 = 0; k0 < 5; k0++) {
            ulonglong2 wv = *(const ulonglong2*)(w2b + k0 * HPAIR + ip2 * 2);
            ffma2(acc[k0], hA, wv.x);
            ffma2(acc[k0], hB, wv.y);
        }
    }
    #pragma unroll
    for (int k0 = 0; k0 < 5; k0++)
        out[k0] = hsum(acc[k0]) + w.B2[half * 5 + k0];
}

__global__ void __launch_bounds__(BLOCK)
jump_euler_kernel(
    const float* __restrict__ z0,
    const float* __restrict__ dW0, const float* __restrict__ db0,
    const float* __restrict__ dW1, const float* __restrict__ db1,
    const float* __restrict__ dW2, const float* __restrict__ db2,
    const float* __restrict__ jW0, const float* __restrict__ jb0,
    const float* __restrict__ jW1, const float* __restrict__ jb1,
    const float* __restrict__ jW2, const float* __restrict__ jb2,
    const float* __restrict__ mean, const float* __restrict__ cov,
    const float* __restrict__ diff,
    const float* __restrict__ pois, const float* __restrict__ nbd,
    const float* __restrict__ nd,
    float* __restrict__ out, int Nsim, int steps)
{
    int tid = threadIdx.x;

    fill_mlp(s_drift, dW0, db0, dW1, db1, dW2, db2, tid);
    fill_mlp(s_jump,  jW0, jb0, jW1, jb1, jW2, jb2, tid);
    for (int idx = tid; idx < D * DPAIR; idx += BLOCK) {
        int k = idx / DPAIR, ip = idx % DPAIR;
        s_cov[k][ip] = pack2(cov[(2 * ip) * D + k], cov[(2 * ip + 1) * D + k]);
    }
    if (tid < D) {
        s_mean[tid]    = mean[tid];
        s_diff[0][tid] = diff[tid];
        s_diff[1][tid] = diff[D + tid];
    }
    __syncthreads();

    int gthread = blockIdx.x * BLOCK + tid;
    int sim  = gthread >> 1;       // two lanes per path (adjacent lanes)
    int half = tid & 1;
    if (sim >= Nsim) return;
    int kbase = half * 5;

    // Full state held as two compile-time-indexed halves.
    float zlo[5], zhi[5];          // components 0..4 / 5..9
    float* orow = out + (size_t)sim * (size_t)(steps + 1) * D;
    {
        const float2* z0v = (const float2*)(z0 + (size_t)sim * D);
        float2 v0 = z0v[0], v1 = z0v[1], v2 = z0v[2], v3 = z0v[3], v4 = z0v[4];
        zlo[0] = v0.x; zlo[1] = v0.y; zlo[2] = v1.x; zlo[3] = v1.y; zlo[4] = v2.x;
        zhi[0] = v2.y; zhi[1] = v3.x; zhi[2] = v3.y; zhi[3] = v4.x; zhi[4] = v4.y;
        // path[:,0,:] = z0 — each lane stores its 5 components
        #pragma unroll
        for (int k0 = 0; k0 < 5; k0++)
            orow[kbase + k0] = half ? zhi[k0] : zlo[k0];
    }

    for (int t = 0; t < steps; t++) {
        size_t base = (size_t)t * Nsim + sim;
        // Prefetch this step's noise early; consumed after ~5K cycles of math.
        float p   = pois[base];
        float2 nb = *(const float2*)(nbd + base * 2);
        u64 ndp[DPAIR];
        {
            const float2* ndv = (const float2*)(nd + base * D);
            #pragma unroll
            for (int ip = 0; ip < DPAIR; ip++) {
                float2 v = ndv[ip];
                ndp[ip] = pack2(v.x, v.y);
            }
        }

        u64 zp[DPAIR];
        zp[0] = pack2(zlo[0], zlo[1]);
        zp[1] = pack2(zlo[2], zlo[3]);
        zp[2] = pack2(zlo[4], zhi[0]);
        zp[3] = pack2(zhi[1], zhi[2]);
        zp[4] = pack2(zhi[3], zhi[4]);

        float drift[5], jmlp[5];
        run_mlp(s_drift, half, zp, drift);
        run_mlp(s_jump,  half, zp, jmlp);

        float sp = sqrtf(p);
        float* orow_t = orow + (size_t)(t + 1) * D;
        float znew[5];
        #pragma unroll
        for (int k0 = 0; k0 < 5; k0++) {
            int k = kbase + k0;                         // shared-mem index (runtime OK)
            u64 a = 0ULL;
            #pragma unroll
            for (int ip = 0; ip < DPAIR; ip++) ffma2(a, ndp[ip], s_cov[k][ip]);
            float covk = hsum(a);
            float ja  = fmaf(p, s_mean[k], sp * covk);                  // jump amp
            float dif = fmaf(nb.x, s_diff[0][k], nb.y * s_diff[1][k]);  // nbd @ diffusion
            float zo  = half ? zhi[k0] : zlo[k0];
            float nz = fmaf(drift[k0], DT_F, zo);
            nz = fmaf(SQDT_F, dif, nz);
            nz = fmaf(ja, jmlp[k0], nz);
            znew[k0] = nz;
            orow_t[k] = nz;                              // store own 5 components
        }
        // Exchange state halves for next step.
        #pragma unroll
        for (int k0 = 0; k0 < 5; k0++) {
            float a = znew[k0];
            float b = shfl1f(a);
            zlo[k0] = half ? b : a;
            zhi[k0] = half ? a : b;
        }
    }
}

extern "C" void kernel_launch(void* const* d_in, const int* in_sizes, int n_in,
                              void* d_out, int out_size)
{
    // metadata order:
    // 0 z0, 1 dW0, 2 db0, 3 dW1, 4 db1, 5 dW2, 6 db2,
    // 7 jW0, 8 jb0, 9 jW1, 10 jb1, 11 jW2, 12 jb2,
    // 13 mean, 14 covHalf, 15 diffusion, 16 pois, 17 noise_bd, 18 noise_d, 19 steps
    const float* z0  = (const float*)d_in[0];
    const float* dW0 = (const float*)d_in[1];
    const float* db0 = (const float*)d_in[2];
    const float* dW1 = (const float*)d_in[3];
    const float* db1 = (const float*)d_in[4];
    const float* dW2 = (const float*)d_in[5];
    const float* db2 = (const float*)d_in[6];
    const float* jW0 = (const float*)d_in[7];
    const float* jb0 = (const float*)d_in[8];
    const float* jW1 = (const float*)d_in[9];
    const float* jb1 = (const float*)d_in[10];
    const float* jW2 = (const float*)d_in[11];
    const float* jb2 = (const float*)d_in[12];
    const float* mean = (const float*)d_in[13];
    const float* cov  = (const float*)d_in[14];
    const float* diff = (const float*)d_in[15];
    const float* pois = (const float*)d_in[16];
    const float* nbd  = (const float*)d_in[17];
    const float* nd   = (const float*)d_in[18];

    int Nsim  = in_sizes[0] / D;
    int steps = in_sizes[16] / Nsim;

    int grid = (Nsim * 2 + BLOCK - 1) / BLOCK;
    jump_euler_kernel<<<grid, BLOCK>>>(
        z0, dW0, db0, dW1, db1, dW2, db2,
        jW0, jb0, jW1, jb1, jW2, jb2,
        mean, cov, diff, pois, nbd, nd,
        (float*)d_out, Nsim, steps);
}